// round 6
// baseline (speedup 1.0000x reference)
#include <cuda_runtime.h>
#include <math.h>

// ---------------- constants ----------------
namespace {
constexpr int B_   = 16;
constexpr int N_   = 8192;
constexpr int BNT  = B_ * N_;       // 131072
constexpr int KNN_ = 16;
constexpr float EPS_ = 1e-5f;

// double-stat segment offsets: [sum(C), sq(C)] per stage
constexpr int ST1 = 0;              // 64 ch  -> 128
constexpr int ST2 = 128;            // 128 ch -> 256
constexpr int ST3 = 384;            // 512 ch -> 1024
constexpr int ST4 = 1408;           // 512 ch -> 1024
constexpr int ST5 = 2432;           // 3 ch   -> 6
constexpr int ST6 = 2438;           // 3 ch   -> 6
constexpr int STTOT = 2444;

// bn (a,b) float segment offsets
constexpr int AB1 = 0;              // 64  -> 128
constexpr int AB2 = 128;            // 128 -> 256
constexpr int AB4 = 384;            // 512 -> 1024
constexpr int AB5 = 1408;           // 3 -> 6
constexpr int AB6 = 1414;           // 3 -> 6
constexpr int ABTOT = 1420;
}

// ---------------- scratch (static device allocations; no cudaMalloc) ----------------
__device__ float    g_Y1[(size_t)BNT * 64];
__device__ float    g_S1[(size_t)BNT * 64];
__device__ float    g_Y2[(size_t)BNT * 128];
__device__ float    g_S2[(size_t)BNT * 128];
__device__ float    g_Y3[(size_t)BNT * 512];
__device__ float    g_Y5[(size_t)BNT * 3];
__device__ float    g_Y6[(size_t)BNT * 3];
__device__ double   g_st[STTOT];
__device__ float    g_ab[ABTOT];
__device__ unsigned g_pmax[B_ * 512];
__device__ unsigned g_pmin[B_ * 512];
__device__ float    g_P[B_ * 512];
__device__ float    g_Y4[B_ * 512];
__device__ float    g_cb1[B_ * 3];
__device__ float    g_cb2[B_ * 3];

// ---------------- helpers ----------------
__device__ __forceinline__ unsigned fenc(float f) {
    unsigned u = __float_as_uint(f);
    return (u & 0x80000000u) ? ~u : (u | 0x80000000u);
}
__device__ __forceinline__ float fdec(unsigned u) {
    u = (u & 0x80000000u) ? (u & 0x7fffffffu) : ~u;
    return __uint_as_float(u);
}

// block-wide reduce of 3-channel (sum, sumsq) -> atomic into st[0..5]
// blockDim.x must be 256 (8 warps)
__device__ __forceinline__ void block_stats3(const float y0, const float y1, const float y2,
                                             double* st) {
    float v[6] = {y0, y1, y2, y0 * y0, y1 * y1, y2 * y2};
#pragma unroll
    for (int i = 0; i < 6; i++)
#pragma unroll
        for (int o = 16; o > 0; o >>= 1)
            v[i] += __shfl_down_sync(0xffffffffu, v[i], o);
    __shared__ float sm[8][6];
    int lane = threadIdx.x & 31, w = threadIdx.x >> 5;
    if (lane == 0) {
#pragma unroll
        for (int i = 0; i < 6; i++) sm[w][i] = v[i];
    }
    __syncthreads();
    if (threadIdx.x < 6) {
        float acc = 0.f;
#pragma unroll
        for (int i = 0; i < 8; i++) acc += sm[i][threadIdx.x];
        atomicAdd(&st[threadIdx.x], (double)acc);
    }
    __syncthreads();
}

// ---------------- kernels ----------------

__global__ void k_init(double* st, unsigned* pmax, unsigned* pmin) {
    int t = blockIdx.x * blockDim.x + threadIdx.x;
    if (t < STTOT) st[t] = 0.0;
    if (t < B_ * 512) { pmax[t] = 0u; pmin[t] = 0xFFFFFFFFu; }
}

// cov features + Linear(12,64); block = 128 threads = 128 nodes
__global__ void k_feat_e1(const float* __restrict__ data, const int* __restrict__ knn,
                          const float* __restrict__ w, const float* __restrict__ bias,
                          float* __restrict__ Y1) {
    __shared__ float ws[12 * 64];
    __shared__ float bs[64];
    __shared__ float xs[128][12];
    int tid = threadIdx.x;
    for (int i = tid; i < 12 * 64; i += 128) ws[i] = w[i];
    if (tid < 64) bs[tid] = bias[tid];

    int tnode = blockIdx.x * 128 + tid;
    int b = tnode >> 13;
    int n = tnode & (N_ - 1);
    const float* db = data + (size_t)b * N_ * 3;
    const int* kn = knn + (size_t)tnode * KNN_;

    float sx = 0, sy = 0, sz = 0;
    float sxx = 0, sxy = 0, sxz = 0, syy = 0, syz = 0, szz = 0;
#pragma unroll
    for (int j = 0; j < KNN_; j++) {
        int id = kn[j];
        float x = db[id * 3 + 0], y = db[id * 3 + 1], z = db[id * 3 + 2];
        sx += x; sy += y; sz += z;
        sxx += x * x; sxy += x * y; sxz += x * z;
        syy += y * y; syz += y * z; szz += z * z;
    }
    const float i16 = 1.f / 16.f, i15 = 1.f / 15.f;
    float mx = sx * i16, my = sy * i16, mz = sz * i16;
    float c00 = (sxx - 16.f * mx * mx) * i15;
    float c01 = (sxy - 16.f * mx * my) * i15;
    float c02 = (sxz - 16.f * mx * mz) * i15;
    float c11 = (syy - 16.f * my * my) * i15;
    float c12 = (syz - 16.f * my * mz) * i15;
    float c22 = (szz - 16.f * mz * mz) * i15;
    xs[tid][0] = db[n * 3 + 0];
    xs[tid][1] = db[n * 3 + 1];
    xs[tid][2] = db[n * 3 + 2];
    xs[tid][3] = c00; xs[tid][4] = c01; xs[tid][5] = c02;
    xs[tid][6] = c01; xs[tid][7] = c11; xs[tid][8] = c12;
    xs[tid][9] = c02; xs[tid][10] = c12; xs[tid][11] = c22;
    __syncthreads();

    int c = tid & 63;
    int ns = tid >> 6;  // 0..1
    size_t rowbase = (size_t)blockIdx.x * 128;
    for (int nr = ns; nr < 128; nr += 2) {
        float y = bs[c];
#pragma unroll
        for (int k = 0; k < 12; k++) y = fmaf(xs[nr][k], ws[k * 64 + c], y);
        Y1[(rowbase + nr) * 64 + c] = y;
    }
}

// per-channel column stats (sum, sumsq) -> double atomics.  blockDim=256, grid=512
template <int C>
__global__ void k_colstats(const float* __restrict__ X, double* __restrict__ st) {
    constexpr int SUB = 256 / C;
    __shared__ float ssum[256], ssq[256];
    int c = threadIdx.x % C;
    int sub = threadIdx.x / C;
    size_t rowbase = (size_t)blockIdx.x * 256;
    float s = 0.f, q = 0.f;
    for (int r = sub; r < 256; r += SUB) {
        float v = X[(rowbase + r) * C + c];
        s += v; q += v * v;
    }
    ssum[threadIdx.x] = s; ssq[threadIdx.x] = q;
    __syncthreads();
    if (threadIdx.x < C) {
        float ts = 0.f, tq = 0.f;
#pragma unroll
        for (int k = 0; k < SUB; k++) { ts += ssum[threadIdx.x + k * C]; tq += ssq[threadIdx.x + k * C]; }
        atomicAdd(&st[threadIdx.x], (double)ts);
        atomicAdd(&st[C + threadIdx.x], (double)tq);
    }
}

__global__ void k_finalize(const double* __restrict__ st, const float* __restrict__ g,
                           const float* __restrict__ be, float* __restrict__ ab,
                           int C, double inv) {
    int c = blockIdx.x * blockDim.x + threadIdx.x;
    if (c < C) {
        float m = (float)(st[c] * inv);
        float v = (float)(st[C + c] * inv) - m * m;
        float a = g[c] * rsqrtf(v + EPS_);
        ab[c] = a;
        ab[C + c] = be[c] - a * m;
    }
}

// S[i] = f(Y[i]) + sum_j f(Y[knn_j]),  f = relu(a*y+b).  warp per node, blockDim=256
template <int C>
__global__ void k_aggregate(const float* __restrict__ Y, const int* __restrict__ knn,
                            const float* __restrict__ ab, float* __restrict__ S) {
    constexpr int V = C / 32;
    int gw = (blockIdx.x * blockDim.x + threadIdx.x) >> 5;
    int lane = threadIdx.x & 31;
    int b = gw >> 13;
    int n = gw & (N_ - 1);
    float av[V], sv[V], acc[V];
#pragma unroll
    for (int v = 0; v < V; v++) {
        av[v] = ab[lane * V + v];
        sv[v] = ab[C + lane * V + v];
        acc[v] = 0.f;
    }
    const int* kn = knn + (size_t)gw * KNN_;
    int idxs[17];
    idxs[0] = n;
#pragma unroll
    for (int j = 0; j < KNN_; j++) idxs[j + 1] = kn[j];
    size_t bbase = (size_t)b * N_;
#pragma unroll 4
    for (int j = 0; j < 17; j++) {
        const float* row = Y + (bbase + idxs[j]) * C;
        if constexpr (C == 64) {
            float2 val = reinterpret_cast<const float2*>(row)[lane];
            acc[0] += fmaxf(fmaf(av[0], val.x, sv[0]), 0.f);
            acc[1] += fmaxf(fmaf(av[1], val.y, sv[1]), 0.f);
        } else {
            float4 val = reinterpret_cast<const float4*>(row)[lane];
            acc[0] += fmaxf(fmaf(av[0], val.x, sv[0]), 0.f);
            acc[1] += fmaxf(fmaf(av[1], val.y, sv[1]), 0.f);
            acc[2] += fmaxf(fmaf(av[2], val.z, sv[2]), 0.f);
            acc[3] += fmaxf(fmaf(av[3], val.w, sv[3]), 0.f);
        }
    }
    float* out = S + (size_t)gw * C;
    if constexpr (C == 64) {
        reinterpret_cast<float2*>(out)[lane] = make_float2(acc[0], acc[1]);
    } else {
        reinterpret_cast<float4*>(out)[lane] = make_float4(acc[0], acc[1], acc[2], acc[3]);
    }
}

// SIMT GEMM: Out[M,ND] = (A[M,KD] @ W[KD,ND]) * scale + bias.  256 thr, 128x128 tile
template <int KD, int ND>
__global__ void __launch_bounds__(256)
k_gemm(const float* __restrict__ A, const float* __restrict__ W,
       const float* __restrict__ bias, float* __restrict__ Out, float scale) {
    constexpr int BM = 128, BNc = 128, BKc = 32;
    __shared__ float As[BM][BKc + 4];   // [128][36]
    __shared__ float Bs[BKc][BNc];
    int tid = threadIdx.x;
    int ty = tid >> 4, tx = tid & 15;
    const float* Ab = A + (size_t)blockIdx.x * BM * KD;
    const float* Wb = W + blockIdx.y * BNc;
    float acc[8][8];
#pragma unroll
    for (int i = 0; i < 8; i++)
#pragma unroll
        for (int j = 0; j < 8; j++) acc[i][j] = 0.f;

    int arow = tid >> 3;          // 0..31
    int acol = (tid & 7) << 2;    // 0..28
    int brow = tid >> 5;          // 0..7
    int bcol = (tid & 31) << 2;   // 0..124

    for (int k0 = 0; k0 < KD; k0 += BKc) {
#pragma unroll
        for (int i = 0; i < 4; i++) {
            float4 v = *reinterpret_cast<const float4*>(Ab + (size_t)(arow + 32 * i) * KD + (k0 + acol));
            *reinterpret_cast<float4*>(&As[arow + 32 * i][acol]) = v;
        }
#pragma unroll
        for (int i = 0; i < 4; i++) {
            float4 v = *reinterpret_cast<const float4*>(Wb + (size_t)(k0 + brow + 8 * i) * ND + bcol);
            *reinterpret_cast<float4*>(&Bs[brow + 8 * i][bcol]) = v;
        }
        __syncthreads();
#pragma unroll
        for (int k = 0; k < BKc; k++) {
            float ar[8], br[8];
#pragma unroll
            for (int i = 0; i < 8; i++) ar[i] = As[ty * 8 + i][k];
            float4 b0 = *reinterpret_cast<const float4*>(&Bs[k][tx * 8]);
            float4 b1 = *reinterpret_cast<const float4*>(&Bs[k][tx * 8 + 4]);
            br[0] = b0.x; br[1] = b0.y; br[2] = b0.z; br[3] = b0.w;
            br[4] = b1.x; br[5] = b1.y; br[6] = b1.z; br[7] = b1.w;
#pragma unroll
            for (int i = 0; i < 8; i++)
#pragma unroll
                for (int j = 0; j < 8; j++) acc[i][j] = fmaf(ar[i], br[j], acc[i][j]);
        }
        __syncthreads();
    }
#pragma unroll
    for (int i = 0; i < 8; i++) {
        size_t row = (size_t)blockIdx.x * BM + ty * 8 + i;
#pragma unroll
        for (int j = 0; j < 8; j += 4) {
            int col = blockIdx.y * BNc + tx * 8 + j;
            float4 bv = *reinterpret_cast<const float4*>(bias + col);
            float4 o;
            o.x = fmaf(acc[i][j + 0], scale, bv.x);
            o.y = fmaf(acc[i][j + 1], scale, bv.y);
            o.z = fmaf(acc[i][j + 2], scale, bv.z);
            o.w = fmaf(acc[i][j + 3], scale, bv.w);
            *reinterpret_cast<float4*>(Out + row * ND + col) = o;
        }
    }
}

// Y3 stats + per-(batch,channel) max/min.  grid(chunk=16, b=16), blockDim=512
__global__ void k_stats_pool(const float* __restrict__ Y3, double* __restrict__ st3,
                             unsigned* __restrict__ pmax, unsigned* __restrict__ pmin) {
    int b = blockIdx.y, chunk = blockIdx.x, c = threadIdx.x;
    const float* base = Y3 + ((size_t)b * N_ + (size_t)chunk * 512) * 512;
    float s = 0.f, q = 0.f, mx = -1e30f, mn = 1e30f;
    for (int r = 0; r < 512; r++) {
        float v = base[(size_t)r * 512 + c];
        s += v; q += v * v;
        mx = fmaxf(mx, v); mn = fminf(mn, v);
    }
    atomicAdd(&st3[c], (double)s);
    atomicAdd(&st3[512 + c], (double)q);
    atomicMax(&pmax[b * 512 + c], fenc(mx));
    atomicMin(&pmin[b * 512 + c], fenc(mn));
}

// bn3 + monotone pooled relu.  grid=16 (batch), blockDim=512
__global__ void k_f3pool(const double* __restrict__ st3, const unsigned* __restrict__ pmax,
                         const unsigned* __restrict__ pmin, const float* __restrict__ g,
                         const float* __restrict__ be, float* __restrict__ P) {
    int b = blockIdx.x, c = threadIdx.x;
    double inv = 1.0 / (double)BNT;
    float m = (float)(st3[c] * inv);
    float v = (float)(st3[512 + c] * inv) - m * m;
    float a = g[c] * rsqrtf(v + EPS_);
    float sh = be[c] - a * m;
    float e = (a >= 0.f) ? fdec(pmax[b * 512 + c]) : fdec(pmin[b * 512 + c]);
    P[b * 512 + c] = fmaxf(fmaf(a, e, sh), 0.f);
}

// e2 linear: Y4 = P @ e2_w + e2_b, plus st4.  grid=16, blockDim=512
__global__ void k_e2(const float* __restrict__ P, const float* __restrict__ w,
                     const float* __restrict__ bias, float* __restrict__ Y4,
                     double* __restrict__ st4) {
    __shared__ float pr[512];
    int b = blockIdx.x, c = threadIdx.x;
    pr[c] = P[b * 512 + c];
    __syncthreads();
    float y = bias[c];
    for (int k = 0; k < 512; k++) y = fmaf(pr[k], w[k * 512 + c], y);
    Y4[b * 512 + c] = y;
    atomicAdd(&st4[c], (double)y);
    atomicAdd(&st4[512 + c], (double)(y * y));
}

// cw = relu(bn4(Y4)); cb1 = cw @ d1_w[:512], cb2 = cw @ d2_w[:512].  grid=16, blockDim=512
__global__ void k_cw(const float* __restrict__ ab4, const float* __restrict__ Y4,
                     const float* __restrict__ d1w, const float* __restrict__ d2w,
                     float* __restrict__ cb1, float* __restrict__ cb2) {
    __shared__ float cwsh[512];
    __shared__ float red[512];
    int b = blockIdx.x, c = threadIdx.x;
    float a = ab4[c], sh = ab4[512 + c];
    cwsh[c] = fmaxf(fmaf(a, Y4[b * 512 + c], sh), 0.f);
    __syncthreads();
    for (int d = 0; d < 6; d++) {
        const float* W = (d < 3) ? d1w : d2w;
        int j = (d < 3) ? d : d - 3;
        red[c] = cwsh[c] * W[c * 3 + j];
        __syncthreads();
        for (int s = 256; s > 0; s >>= 1) {
            if (c < s) red[c] += red[c + s];
            __syncthreads();
        }
        if (c == 0) { ((d < 3) ? cb1 : cb2)[b * 3 + j] = red[0]; }
        __syncthreads();
    }
}

// decode stage 1: Y5 = cb1[b] + grid @ d1_w[512:514] + d1_b, + st5.  grid=512, blockDim=256
__global__ void k_decode1(const float* __restrict__ cb1, const float* __restrict__ d1w,
                          const float* __restrict__ d1b, float* __restrict__ Y5,
                          double* __restrict__ st5) {
    int t = blockIdx.x * 256 + threadIdx.x;
    int b = t >> 13, n = t & (N_ - 1);
    int ix = n / 65, iy = n % 65;
    float gx = 1.f + (float)ix * (119.f / 128.f);
    float gy = 1.f + (float)iy * (59.f / 64.f);
    float y[3];
#pragma unroll
    for (int j = 0; j < 3; j++) {
        y[j] = cb1[b * 3 + j] + gx * d1w[512 * 3 + j] + gy * d1w[513 * 3 + j] + d1b[j];
        Y5[(size_t)t * 3 + j] = y[j];
    }
    block_stats3(y[0], y[1], y[2], st5);
}

// decode stage 2: z1 = relu(bn5(Y5)); Y6 = cb2[b] + z1 @ d2_w[512:515] + d2_b, + st6
__global__ void k_decode2(const float* __restrict__ Y5, const float* __restrict__ ab5,
                          const float* __restrict__ cb2, const float* __restrict__ d2w,
                          const float* __restrict__ d2b, float* __restrict__ Y6,
                          double* __restrict__ st6) {
    int t = blockIdx.x * 256 + threadIdx.x;
    int b = t >> 13;
    float z[3];
#pragma unroll
    for (int i = 0; i < 3; i++) {
        float v = Y5[(size_t)t * 3 + i];
        z[i] = fmaxf(fmaf(ab5[i], v, ab5[3 + i]), 0.f);
    }
    float y[3];
#pragma unroll
    for (int j = 0; j < 3; j++) {
        float v = cb2[b * 3 + j] + d2b[j];
#pragma unroll
        for (int i = 0; i < 3; i++) v = fmaf(z[i], d2w[(512 + i) * 3 + j], v);
        y[j] = v;
        Y6[(size_t)t * 3 + j] = v;
    }
    block_stats3(y[0], y[1], y[2], st6);
}

__global__ void k_out(const float* __restrict__ Y6, const float* __restrict__ ab6,
                      float* __restrict__ out) {
    int t = blockIdx.x * 256 + threadIdx.x;
#pragma unroll
    for (int j = 0; j < 3; j++) {
        float v = Y6[(size_t)t * 3 + j];
        out[(size_t)t * 3 + j] = fmaxf(fmaf(ab6[j], v, ab6[3 + j]), 0.f);
    }
}

// ---------------- launch ----------------
extern "C" void kernel_launch(void* const* d_in, const int* in_sizes, int n_in,
                              void* d_out, int out_size) {
    (void)in_sizes; (void)n_in; (void)out_size;
    const float* data  = (const float*)d_in[0];
    const int*   knn   = (const int*)d_in[1];
    const float* e1_w  = (const float*)d_in[2];
    const float* e1_b  = (const float*)d_in[3];
    const float* e1_g  = (const float*)d_in[4];
    const float* e1_be = (const float*)d_in[5];
    const float* gc1_w = (const float*)d_in[6];
    const float* gc1_b = (const float*)d_in[7];
    const float* g1_g  = (const float*)d_in[8];
    const float* g1_be = (const float*)d_in[9];
    const float* gc2_w = (const float*)d_in[10];
    const float* gc2_b = (const float*)d_in[11];
    const float* g2_g  = (const float*)d_in[12];
    const float* g2_be = (const float*)d_in[13];
    const float* e2_w  = (const float*)d_in[14];
    const float* e2_b  = (const float*)d_in[15];
    const float* e2_g  = (const float*)d_in[16];
    const float* e2_be = (const float*)d_in[17];
    const float* d1_w  = (const float*)d_in[18];
    const float* d1_b  = (const float*)d_in[19];
    const float* d1_g  = (const float*)d_in[20];
    const float* d1_be = (const float*)d_in[21];
    const float* d2_w  = (const float*)d_in[22];
    const float* d2_b  = (const float*)d_in[23];
    const float* d2_g  = (const float*)d_in[24];
    const float* d2_be = (const float*)d_in[25];
    float* out = (float*)d_out;

    float *Y1, *S1, *Y2, *S2, *Y3, *Y5, *Y6, *ab, *P, *Y4, *cb1, *cb2;
    double* st;
    unsigned *pmax, *pmin;
    cudaGetSymbolAddress((void**)&Y1, g_Y1);
    cudaGetSymbolAddress((void**)&S1, g_S1);
    cudaGetSymbolAddress((void**)&Y2, g_Y2);
    cudaGetSymbolAddress((void**)&S2, g_S2);
    cudaGetSymbolAddress((void**)&Y3, g_Y3);
    cudaGetSymbolAddress((void**)&Y5, g_Y5);
    cudaGetSymbolAddress((void**)&Y6, g_Y6);
    cudaGetSymbolAddress((void**)&st, g_st);
    cudaGetSymbolAddress((void**)&ab, g_ab);
    cudaGetSymbolAddress((void**)&pmax, g_pmax);
    cudaGetSymbolAddress((void**)&pmin, g_pmin);
    cudaGetSymbolAddress((void**)&P, g_P);
    cudaGetSymbolAddress((void**)&Y4, g_Y4);
    cudaGetSymbolAddress((void**)&cb1, g_cb1);
    cudaGetSymbolAddress((void**)&cb2, g_cb2);

    const double invBN = 1.0 / (double)BNT;

    k_init<<<32, 256>>>(st, pmax, pmin);

    // features + e1 linear
    k_feat_e1<<<BNT / 128, 128>>>(data, knn, e1_w, e1_b, Y1);
    k_colstats<64><<<512, 256>>>(Y1, st + ST1);
    k_finalize<<<1, 256>>>(st + ST1, e1_g, e1_be, ab + AB1, 64, invBN);

    // gcn1: aggregate (fused bn+relu) then linear
    k_aggregate<64><<<BNT / 8, 256>>>(Y1, knn, ab + AB1, S1);
    k_gemm<64, 128><<<dim3(BNT / 128, 1), 256>>>(S1, gc1_w, gc1_b, Y2, 1.f / 17.f);
    k_colstats<128><<<512, 256>>>(Y2, st + ST2);
    k_finalize<<<1, 256>>>(st + ST2, g1_g, g1_be, ab + AB2, 128, invBN);

    // gcn2
    k_aggregate<128><<<BNT / 8, 256>>>(Y2, knn, ab + AB2, S2);
    k_gemm<128, 512><<<dim3(BNT / 128, 4), 256>>>(S2, gc2_w, gc2_b, Y3, 1.f / 17.f);

    // bn3 stats + per-(b,c) extrema, then pooled relu
    k_stats_pool<<<dim3(16, 16), 512>>>(Y3, st + ST3, pmax, pmin);
    k_f3pool<<<16, 512>>>(st + ST3, pmax, pmin, g2_g, g2_be, P);

    // e2 linear + bn4 (over 16 samples) + codeword projections
    k_e2<<<16, 512>>>(P, e2_w, e2_b, Y4, st + ST4);
    k_finalize<<<2, 256>>>(st + ST4, e2_g, e2_be, ab + AB4, 512, 1.0 / 16.0);
    k_cw<<<16, 512>>>(ab + AB4, Y4, d1_w, d2_w, cb1, cb2);

    // decode
    k_decode1<<<BNT / 256, 256>>>(cb1, d1_w, d1_b, Y5, st + ST5);
    k_finalize<<<1, 32>>>(st + ST5, d1_g, d1_be, ab + AB5, 3, invBN);
    k_decode2<<<BNT / 256, 256>>>(Y5, ab + AB5, cb2, d2_w, d2_b, Y6, st + ST6);
    k_finalize<<<1, 32>>>(st + ST6, d2_g, d2_be, ab + AB6, 3, invBN);
    k_out<<<BNT / 256, 256>>>(Y6, ab + AB6, out);
}

// round 11
// speedup vs baseline: 1.3142x; 1.3142x over previous
#include <cuda_runtime.h>
#include <math.h>
#include <stdint.h>

// ---------------- constants ----------------
namespace {
constexpr int B_   = 16;
constexpr int N_   = 8192;
constexpr int BNT  = B_ * N_;       // 131072
constexpr int KNN_ = 16;
constexpr float EPS_ = 1e-5f;

// double-stat segment offsets: [sum(C), sq(C)] per stage
constexpr int ST1 = 0;              // 64 ch  -> 128
constexpr int ST2 = 128;            // 128 ch -> 256
constexpr int ST3 = 384;            // 512 ch -> 1024
constexpr int ST4 = 1408;           // 512 ch -> 1024
constexpr int ST5 = 2432;           // 3 ch   -> 6
constexpr int ST6 = 2438;           // 3 ch   -> 6
constexpr int STTOT = 2444;

// bn (a,b) float segment offsets
constexpr int AB1 = 0;              // 64  -> 128
constexpr int AB2 = 128;            // 128 -> 256
constexpr int AB4 = 384;            // 512 -> 1024
constexpr int AB5 = 1408;           // 3 -> 6
constexpr int AB6 = 1414;           // 3 -> 6
constexpr int ABTOT = 1420;
}

// ---------------- scratch (static device allocations; no cudaMalloc) ----------------
__device__ float    g_Y1[(size_t)BNT * 64];
__device__ float    g_S1[(size_t)BNT * 64];
__device__ float    g_Y2[(size_t)BNT * 128];
__device__ float    g_S2[(size_t)BNT * 128];
__device__ float    g_Y5[(size_t)BNT * 3];
__device__ float    g_Y6[(size_t)BNT * 3];
__device__ double   g_st[STTOT];
__device__ float    g_ab[ABTOT];
__device__ unsigned g_pmax[B_ * 512];
__device__ unsigned g_pmin[B_ * 512];
__device__ float    g_P[B_ * 512];
__device__ float    g_Y4[B_ * 512];
__device__ float    g_cb1[B_ * 3];
__device__ float    g_cb2[B_ * 3];

// ---------------- helpers ----------------
__device__ __forceinline__ unsigned fenc(float f) {
    unsigned u = __float_as_uint(f);
    return (u & 0x80000000u) ? ~u : (u | 0x80000000u);
}
__device__ __forceinline__ float fdec(unsigned u) {
    u = (u & 0x80000000u) ? (u & 0x7fffffffu) : ~u;
    return __uint_as_float(u);
}
__device__ __forceinline__ uint32_t f2tf(float f) {
    uint32_t u;
    asm("cvt.rna.tf32.f32 %0, %1;" : "=r"(u) : "f"(f));
    return u;
}
// split x into tf32 hi + tf32 lo (hi + lo carries ~22 mantissa bits)
__device__ __forceinline__ void tfsplit(float x, uint32_t& hi, uint32_t& lo) {
    hi = f2tf(x);
    lo = f2tf(x - __uint_as_float(hi));
}
__device__ __forceinline__ void mma_tf32(float c[4], uint32_t a0, uint32_t a1,
                                         uint32_t a2, uint32_t a3,
                                         uint32_t b0, uint32_t b1) {
    asm volatile(
        "mma.sync.aligned.m16n8k8.row.col.f32.tf32.tf32.f32 "
        "{%0,%1,%2,%3}, {%4,%5,%6,%7}, {%8,%9}, {%0,%1,%2,%3};"
        : "+f"(c[0]), "+f"(c[1]), "+f"(c[2]), "+f"(c[3])
        : "r"(a0), "r"(a1), "r"(a2), "r"(a3), "r"(b0), "r"(b1));
}

// block-wide reduce of 3-channel (sum, sumsq) -> atomic into st[0..5]
// blockDim.x must be 256 (8 warps)
__device__ __forceinline__ void block_stats3(const float y0, const float y1, const float y2,
                                             double* st) {
    float v[6] = {y0, y1, y2, y0 * y0, y1 * y1, y2 * y2};
#pragma unroll
    for (int i = 0; i < 6; i++)
#pragma unroll
        for (int o = 16; o > 0; o >>= 1)
            v[i] += __shfl_down_sync(0xffffffffu, v[i], o);
    __shared__ float sm[8][6];
    int lane = threadIdx.x & 31, w = threadIdx.x >> 5;
    if (lane == 0) {
#pragma unroll
        for (int i = 0; i < 6; i++) sm[w][i] = v[i];
    }
    __syncthreads();
    if (threadIdx.x < 6) {
        float acc = 0.f;
#pragma unroll
        for (int i = 0; i < 8; i++) acc += sm[i][threadIdx.x];
        atomicAdd(&st[threadIdx.x], (double)acc);
    }
    __syncthreads();
}

// ---------------- kernels ----------------

__global__ void k_init(double* st, unsigned* pmax, unsigned* pmin) {
    int t = blockIdx.x * blockDim.x + threadIdx.x;
    if (t < STTOT) st[t] = 0.0;
    if (t < B_ * 512) { pmax[t] = 0u; pmin[t] = 0xFFFFFFFFu; }
}

// cov features + Linear(12,64) + fused column stats; block = 128 threads = 128 nodes
__global__ void k_feat_e1(const float* __restrict__ data, const int* __restrict__ knn,
                          const float* __restrict__ w, const float* __restrict__ bias,
                          float* __restrict__ Y1, double* __restrict__ st1) {
    __shared__ float ws[12 * 64];
    __shared__ float bs[64];
    __shared__ float xs[128][12];
    __shared__ float sred[128], qred[128];
    int tid = threadIdx.x;
    for (int i = tid; i < 12 * 64; i += 128) ws[i] = w[i];
    if (tid < 64) bs[tid] = bias[tid];

    int tnode = blockIdx.x * 128 + tid;
    int b = tnode >> 13;
    int n = tnode & (N_ - 1);
    const float* db = data + (size_t)b * N_ * 3;
    const int* kn = knn + (size_t)tnode * KNN_;

    float sx = 0, sy = 0, sz = 0;
    float sxx = 0, sxy = 0, sxz = 0, syy = 0, syz = 0, szz = 0;
#pragma unroll
    for (int j = 0; j < KNN_; j++) {
        int id = kn[j];
        float x = db[id * 3 + 0], y = db[id * 3 + 1], z = db[id * 3 + 2];
        sx += x; sy += y; sz += z;
        sxx += x * x; sxy += x * y; sxz += x * z;
        syy += y * y; syz += y * z; szz += z * z;
    }
    const float i16 = 1.f / 16.f, i15 = 1.f / 15.f;
    float mx = sx * i16, my = sy * i16, mz = sz * i16;
    float c00 = (sxx - 16.f * mx * mx) * i15;
    float c01 = (sxy - 16.f * mx * my) * i15;
    float c02 = (sxz - 16.f * mx * mz) * i15;
    float c11 = (syy - 16.f * my * my) * i15;
    float c12 = (syz - 16.f * my * mz) * i15;
    float c22 = (szz - 16.f * mz * mz) * i15;
    xs[tid][0] = db[n * 3 + 0];
    xs[tid][1] = db[n * 3 + 1];
    xs[tid][2] = db[n * 3 + 2];
    xs[tid][3] = c00; xs[tid][4] = c01; xs[tid][5] = c02;
    xs[tid][6] = c01; xs[tid][7] = c11; xs[tid][8] = c12;
    xs[tid][9] = c02; xs[tid][10] = c12; xs[tid][11] = c22;
    __syncthreads();

    int c = tid & 63;
    int ns = tid >> 6;  // 0..1
    size_t rowbase = (size_t)blockIdx.x * 128;
    float ssum = 0.f, sq = 0.f;
    for (int nr = ns; nr < 128; nr += 2) {
        float y = bs[c];
#pragma unroll
        for (int k = 0; k < 12; k++) y = fmaf(xs[nr][k], ws[k * 64 + c], y);
        Y1[(rowbase + nr) * 64 + c] = y;
        ssum += y; sq += y * y;
    }
    sred[tid] = ssum; qred[tid] = sq;
    __syncthreads();
    if (tid < 64) {
        atomicAdd(&st1[tid], (double)(sred[tid] + sred[tid + 64]));
        atomicAdd(&st1[64 + tid], (double)(qred[tid] + qred[tid + 64]));
    }
}

__global__ void k_finalize(const double* __restrict__ st, const float* __restrict__ g,
                           const float* __restrict__ be, float* __restrict__ ab,
                           int C, double inv) {
    int c = blockIdx.x * blockDim.x + threadIdx.x;
    if (c < C) {
        float m = (float)(st[c] * inv);
        float v = (float)(st[C + c] * inv) - m * m;
        float a = g[c] * rsqrtf(v + EPS_);
        ab[c] = a;
        ab[C + c] = be[c] - a * m;
    }
}

// S[i] = f(Y[i]) + sum_j f(Y[knn_j]),  f = relu(a*y+b).  warp per node, blockDim=256
template <int C>
__global__ void k_aggregate(const float* __restrict__ Y, const int* __restrict__ knn,
                            const float* __restrict__ ab, float* __restrict__ S) {
    constexpr int V = C / 32;
    int gw = (blockIdx.x * blockDim.x + threadIdx.x) >> 5;
    int lane = threadIdx.x & 31;
    int b = gw >> 13;
    int n = gw & (N_ - 1);
    float av[V], sv[V], acc[V];
#pragma unroll
    for (int v = 0; v < V; v++) {
        av[v] = ab[lane * V + v];
        sv[v] = ab[C + lane * V + v];
        acc[v] = 0.f;
    }
    const int* kn = knn + (size_t)gw * KNN_;
    int idxs[17];
    idxs[0] = n;
#pragma unroll
    for (int j = 0; j < KNN_; j++) idxs[j + 1] = kn[j];
    size_t bbase = (size_t)b * N_;
#pragma unroll 4
    for (int j = 0; j < 17; j++) {
        const float* row = Y + (bbase + idxs[j]) * C;
        if constexpr (C == 64) {
            float2 val = reinterpret_cast<const float2*>(row)[lane];
            acc[0] += fmaxf(fmaf(av[0], val.x, sv[0]), 0.f);
            acc[1] += fmaxf(fmaf(av[1], val.y, sv[1]), 0.f);
        } else {
            float4 val = reinterpret_cast<const float4*>(row)[lane];
            acc[0] += fmaxf(fmaf(av[0], val.x, sv[0]), 0.f);
            acc[1] += fmaxf(fmaf(av[1], val.y, sv[1]), 0.f);
            acc[2] += fmaxf(fmaf(av[2], val.z, sv[2]), 0.f);
            acc[3] += fmaxf(fmaf(av[3], val.w, sv[3]), 0.f);
        }
    }
    float* out = S + (size_t)gw * C;
    if constexpr (C == 64) {
        reinterpret_cast<float2*>(out)[lane] = make_float2(acc[0], acc[1]);
    } else {
        reinterpret_cast<float4*>(out)[lane] = make_float4(acc[0], acc[1], acc[2], acc[3]);
    }
}

// ---------------- error-compensated TF32 tensor GEMM (3-MMA split) ----------------
// Out[M,ND] = (A[M,KD] @ W[KD,ND]) * scale + bias.
// Each operand is split into tf32 hi+lo; products hi*hi + lo*hi + hi*lo are
// accumulated (fp32), recovering ~fp32 precision on the tensor pipe.
// Fused epilogue: column sums/sumsq -> st; optional per-(batch,col) extrema.
// 256 threads = 8 warps (2 M x 4 N), 128x128 tile, warp tile 64x32, m16n8k8.
template <int KD, int ND, bool STORE, bool EXTREMA>
__global__ void __launch_bounds__(256)
k_gemm_mma(const float* __restrict__ A, const float* __restrict__ W,
           const float* __restrict__ bias, float* __restrict__ Out, float scale,
           double* __restrict__ st, unsigned* __restrict__ pmax,
           unsigned* __restrict__ pmin) {
    constexpr int LDA = 36;    // As[m][k], k-stride padded (conflict-free frag reads)
    constexpr int LDB = 136;   // Bs[k][n], n-stride padded (conflict-free frag reads)
    extern __shared__ uint32_t smx[];
    uint32_t* As_h = smx;                       // 128*LDA
    uint32_t* As_l = As_h + 128 * LDA;          // 128*LDA
    uint32_t* Bs_h = As_l + 128 * LDA;          // 32*LDB
    uint32_t* Bs_l = Bs_h + 32 * LDB;           // 32*LDB

    int tid = threadIdx.x;
    int lane = tid & 31, wid = tid >> 5;
    int warp_m = wid >> 2, warp_n = wid & 3;
    size_t bm0 = (size_t)blockIdx.x * 128;
    int bn0 = blockIdx.y * 128;

    float acc[4][4][4];
#pragma unroll
    for (int i = 0; i < 4; i++)
#pragma unroll
        for (int j = 0; j < 4; j++)
#pragma unroll
            for (int r = 0; r < 4; r++) acc[i][j][r] = 0.f;

    int am = tid >> 3;           // 0..31
    int ak = (tid & 7) * 4;      // 0..28
    int bkr = tid >> 5;          // 0..7
    int bnc = (tid & 31) * 4;    // 0..124

    for (int k0 = 0; k0 < KD; k0 += 32) {
#pragma unroll
        for (int i = 0; i < 4; i++) {
            int m = am + 32 * i;
            float4 v = *reinterpret_cast<const float4*>(A + (bm0 + m) * KD + k0 + ak);
            uint4 h4, l4;
            tfsplit(v.x, h4.x, l4.x); tfsplit(v.y, h4.y, l4.y);
            tfsplit(v.z, h4.z, l4.z); tfsplit(v.w, h4.w, l4.w);
            *reinterpret_cast<uint4*>(&As_h[m * LDA + ak]) = h4;
            *reinterpret_cast<uint4*>(&As_l[m * LDA + ak]) = l4;
        }
#pragma unroll
        for (int i = 0; i < 4; i++) {
            int k = bkr + 8 * i;
            float4 v = *reinterpret_cast<const float4*>(W + (size_t)(k0 + k) * ND + bn0 + bnc);
            uint4 h4, l4;
            tfsplit(v.x, h4.x, l4.x); tfsplit(v.y, h4.y, l4.y);
            tfsplit(v.z, h4.z, l4.z); tfsplit(v.w, h4.w, l4.w);
            *reinterpret_cast<uint4*>(&Bs_h[k * LDB + bnc]) = h4;
            *reinterpret_cast<uint4*>(&Bs_l[k * LDB + bnc]) = l4;
        }
        __syncthreads();
#pragma unroll
        for (int ks = 0; ks < 4; ks++) {
            int kk = ks * 8 + (lane & 3);
            uint32_t bh[4][2], bl[4][2];
#pragma unroll
            for (int nt = 0; nt < 4; nt++) {
                int n = warp_n * 32 + nt * 8 + (lane >> 2);
                bh[nt][0] = Bs_h[kk * LDB + n];
                bh[nt][1] = Bs_h[(kk + 4) * LDB + n];
                bl[nt][0] = Bs_l[kk * LDB + n];
                bl[nt][1] = Bs_l[(kk + 4) * LDB + n];
            }
#pragma unroll
            for (int mt = 0; mt < 4; mt++) {
                int r = warp_m * 64 + mt * 16 + (lane >> 2);
                uint32_t ah0 = As_h[r * LDA + kk];
                uint32_t ah1 = As_h[(r + 8) * LDA + kk];
                uint32_t ah2 = As_h[r * LDA + kk + 4];
                uint32_t ah3 = As_h[(r + 8) * LDA + kk + 4];
                uint32_t al0 = As_l[r * LDA + kk];
                uint32_t al1 = As_l[(r + 8) * LDA + kk];
                uint32_t al2 = As_l[r * LDA + kk + 4];
                uint32_t al3 = As_l[(r + 8) * LDA + kk + 4];
#pragma unroll
                for (int nt = 0; nt < 4; nt++) {
                    mma_tf32(acc[mt][nt], al0, al1, al2, al3, bh[nt][0], bh[nt][1]);
                    mma_tf32(acc[mt][nt], ah0, ah1, ah2, ah3, bl[nt][0], bl[nt][1]);
                    mma_tf32(acc[mt][nt], ah0, ah1, ah2, ah3, bh[nt][0], bh[nt][1]);
                }
            }
        }
        __syncthreads();
    }

    // ---- epilogue: scale+bias, optional store, fused column stats ----
    float bsv[8];
#pragma unroll
    for (int nt = 0; nt < 4; nt++) {
        int c0 = bn0 + warp_n * 32 + nt * 8 + (lane & 3) * 2;
        bsv[nt * 2 + 0] = bias[c0];
        bsv[nt * 2 + 1] = bias[c0 + 1];
    }
    float s[8], q[8], mxv[8], mnv[8];
#pragma unroll
    for (int i = 0; i < 8; i++) { s[i] = 0.f; q[i] = 0.f; mxv[i] = -3.4e38f; mnv[i] = 3.4e38f; }

#pragma unroll
    for (int mt = 0; mt < 4; mt++) {
        size_t r = bm0 + warp_m * 64 + mt * 16 + (lane >> 2);
#pragma unroll
        for (int nt = 0; nt < 4; nt++) {
            float y0 = fmaf(acc[mt][nt][0], scale, bsv[nt * 2 + 0]);
            float y1 = fmaf(acc[mt][nt][1], scale, bsv[nt * 2 + 1]);
            float y2 = fmaf(acc[mt][nt][2], scale, bsv[nt * 2 + 0]);
            float y3 = fmaf(acc[mt][nt][3], scale, bsv[nt * 2 + 1]);
            if constexpr (STORE) {
                int c0 = bn0 + warp_n * 32 + nt * 8 + (lane & 3) * 2;
                *reinterpret_cast<float2*>(Out + r * ND + c0) = make_float2(y0, y1);
                *reinterpret_cast<float2*>(Out + (r + 8) * ND + c0) = make_float2(y2, y3);
            }
            int i0 = nt * 2, i1 = nt * 2 + 1;
            s[i0] += y0 + y2; q[i0] += y0 * y0 + y2 * y2;
            s[i1] += y1 + y3; q[i1] += y1 * y1 + y3 * y3;
            if constexpr (EXTREMA) {
                mxv[i0] = fmaxf(mxv[i0], fmaxf(y0, y2));
                mnv[i0] = fminf(mnv[i0], fminf(y0, y2));
                mxv[i1] = fmaxf(mxv[i1], fmaxf(y1, y3));
                mnv[i1] = fminf(mnv[i1], fminf(y1, y3));
            }
        }
    }
    // reduce across lanes sharing a column (lane>>2 axis): xor offsets 4,8,16
#pragma unroll
    for (int o = 4; o <= 16; o <<= 1) {
#pragma unroll
        for (int i = 0; i < 8; i++) {
            s[i] += __shfl_xor_sync(0xffffffffu, s[i], o);
            q[i] += __shfl_xor_sync(0xffffffffu, q[i], o);
            if constexpr (EXTREMA) {
                mxv[i] = fmaxf(mxv[i], __shfl_xor_sync(0xffffffffu, mxv[i], o));
                mnv[i] = fminf(mnv[i], __shfl_xor_sync(0xffffffffu, mnv[i], o));
            }
        }
    }
    if (lane < 4) {
        int b = (int)(bm0 >> 13);
#pragma unroll
        for (int i = 0; i < 8; i++) {
            int c = bn0 + warp_n * 32 + (i >> 1) * 8 + lane * 2 + (i & 1);
            atomicAdd(&st[c], (double)s[i]);
            atomicAdd(&st[ND + c], (double)q[i]);
            if constexpr (EXTREMA) {
                atomicMax(&pmax[b * 512 + c], fenc(mxv[i]));
                atomicMin(&pmin[b * 512 + c], fenc(mnv[i]));
            }
        }
    }
}

// bn3 + monotone pooled relu.  grid=16 (batch), blockDim=512
__global__ void k_f3pool(const double* __restrict__ st3, const unsigned* __restrict__ pmax,
                         const unsigned* __restrict__ pmin, const float* __restrict__ g,
                         const float* __restrict__ be, float* __restrict__ P) {
    int b = blockIdx.x, c = threadIdx.x;
    double inv = 1.0 / (double)BNT;
    float m = (float)(st3[c] * inv);
    float v = (float)(st3[512 + c] * inv) - m * m;
    float a = g[c] * rsqrtf(v + EPS_);
    float sh = be[c] - a * m;
    float e = (a >= 0.f) ? fdec(pmax[b * 512 + c]) : fdec(pmin[b * 512 + c]);
    P[b * 512 + c] = fmaxf(fmaf(a, e, sh), 0.f);
}

// e2 linear: Y4 = P @ e2_w + e2_b, plus st4.  grid=16, blockDim=512
__global__ void k_e2(const float* __restrict__ P, const float* __restrict__ w,
                     const float* __restrict__ bias, float* __restrict__ Y4,
                     double* __restrict__ st4) {
    __shared__ float pr[512];
    int b = blockIdx.x, c = threadIdx.x;
    pr[c] = P[b * 512 + c];
    __syncthreads();
    float y = bias[c];
    for (int k = 0; k < 512; k++) y = fmaf(pr[k], w[k * 512 + c], y);
    Y4[b * 512 + c] = y;
    atomicAdd(&st4[c], (double)y);
    atomicAdd(&st4[512 + c], (double)(y * y));
}

// cw = relu(bn4(Y4)); cb1 = cw @ d1_w[:512], cb2 = cw @ d2_w[:512].  grid=16, blockDim=512
__global__ void k_cw(const float* __restrict__ ab4, const float* __restrict__ Y4,
                     const float* __restrict__ d1w, const float* __restrict__ d2w,
                     float* __restrict__ cb1, float* __restrict__ cb2) {
    __shared__ float cwsh[512];
    __shared__ float red[512];
    int b = blockIdx.x, c = threadIdx.x;
    float a = ab4[c], sh = ab4[512 + c];
    cwsh[c] = fmaxf(fmaf(a, Y4[b * 512 + c], sh), 0.f);
    __syncthreads();
    for (int d = 0; d < 6; d++) {
        const float* W = (d < 3) ? d1w : d2w;
        int j = (d < 3) ? d : d - 3;
        red[c] = cwsh[c] * W[c * 3 + j];
        __syncthreads();
        for (int s = 256; s > 0; s >>= 1) {
            if (c < s) red[c] += red[c + s];
            __syncthreads();
        }
        if (c == 0) { ((d < 3) ? cb1 : cb2)[b * 3 + j] = red[0]; }
        __syncthreads();
    }
}

// decode stage 1: Y5 = cb1[b] + grid @ d1_w[512:514] + d1_b, + st5.  blockDim=256
__global__ void k_decode1(const float* __restrict__ cb1, const float* __restrict__ d1w,
                          const float* __restrict__ d1b, float* __restrict__ Y5,
                          double* __restrict__ st5) {
    int t = blockIdx.x * 256 + threadIdx.x;
    int b = t >> 13, n = t & (N_ - 1);
    int ix = n / 65, iy = n % 65;
    float gx = 1.f + (float)ix * (119.f / 128.f);
    float gy = 1.f + (float)iy * (59.f / 64.f);
    float y[3];
#pragma unroll
    for (int j = 0; j < 3; j++) {
        y[j] = cb1[b * 3 + j] + gx * d1w[512 * 3 + j] + gy * d1w[513 * 3 + j] + d1b[j];
        Y5[(size_t)t * 3 + j] = y[j];
    }
    block_stats3(y[0], y[1], y[2], st5);
}

// decode stage 2: z1 = relu(bn5(Y5)); Y6 = cb2[b] + z1 @ d2_w[512:515] + d2_b, + st6
__global__ void k_decode2(const float* __restrict__ Y5, const float* __restrict__ ab5,
                          const float* __restrict__ cb2, const float* __restrict__ d2w,
                          const float* __restrict__ d2b, float* __restrict__ Y6,
                          double* __restrict__ st6) {
    int t = blockIdx.x * 256 + threadIdx.x;
    int b = t >> 13;
    float z[3];
#pragma unroll
    for (int i = 0; i < 3; i++) {
        float v = Y5[(size_t)t * 3 + i];
        z[i] = fmaxf(fmaf(ab5[i], v, ab5[3 + i]), 0.f);
    }
    float y[3];
#pragma unroll
    for (int j = 0; j < 3; j++) {
        float v = cb2[b * 3 + j] + d2b[j];
#pragma unroll
        for (int i = 0; i < 3; i++) v = fmaf(z[i], d2w[(512 + i) * 3 + j], v);
        y[j] = v;
        Y6[(size_t)t * 3 + j] = v;
    }
    block_stats3(y[0], y[1], y[2], st6);
}

__global__ void k_out(const float* __restrict__ Y6, const float* __restrict__ ab6,
                      float* __restrict__ out) {
    int t = blockIdx.x * 256 + threadIdx.x;
#pragma unroll
    for (int j = 0; j < 3; j++) {
        float v = Y6[(size_t)t * 3 + j];
        out[(size_t)t * 3 + j] = fmaxf(fmaf(ab6[j], v, ab6[3 + j]), 0.f);
    }
}

// ---------------- launch ----------------
extern "C" void kernel_launch(void* const* d_in, const int* in_sizes, int n_in,
                              void* d_out, int out_size) {
    (void)in_sizes; (void)n_in; (void)out_size;
    const float* data  = (const float*)d_in[0];
    const int*   knn   = (const int*)d_in[1];
    const float* e1_w  = (const float*)d_in[2];
    const float* e1_b  = (const float*)d_in[3];
    const float* e1_g  = (const float*)d_in[4];
    const float* e1_be = (const float*)d_in[5];
    const float* gc1_w = (const float*)d_in[6];
    const float* gc1_b = (const float*)d_in[7];
    const float* g1_g  = (const float*)d_in[8];
    const float* g1_be = (const float*)d_in[9];
    const float* gc2_w = (const float*)d_in[10];
    const float* gc2_b = (const float*)d_in[11];
    const float* g2_g  = (const float*)d_in[12];
    const float* g2_be = (const float*)d_in[13];
    const float* e2_w  = (const float*)d_in[14];
    const float* e2_b  = (const float*)d_in[15];
    const float* e2_g  = (const float*)d_in[16];
    const float* e2_be = (const float*)d_in[17];
    const float* d1_w  = (const float*)d_in[18];
    const float* d1_b  = (const float*)d_in[19];
    const float* d1_g  = (const float*)d_in[20];
    const float* d1_be = (const float*)d_in[21];
    const float* d2_w  = (const float*)d_in[22];
    const float* d2_b  = (const float*)d_in[23];
    const float* d2_g  = (const float*)d_in[24];
    const float* d2_be = (const float*)d_in[25];
    float* out = (float*)d_out;

    float *Y1, *S1, *Y2, *S2, *Y5, *Y6, *ab, *P, *Y4, *cb1, *cb2;
    double* st;
    unsigned *pmax, *pmin;
    cudaGetSymbolAddress((void**)&Y1, g_Y1);
    cudaGetSymbolAddress((void**)&S1, g_S1);
    cudaGetSymbolAddress((void**)&Y2, g_Y2);
    cudaGetSymbolAddress((void**)&S2, g_S2);
    cudaGetSymbolAddress((void**)&Y5, g_Y5);
    cudaGetSymbolAddress((void**)&Y6, g_Y6);
    cudaGetSymbolAddress((void**)&st, g_st);
    cudaGetSymbolAddress((void**)&ab, g_ab);
    cudaGetSymbolAddress((void**)&pmax, g_pmax);
    cudaGetSymbolAddress((void**)&pmin, g_pmin);
    cudaGetSymbolAddress((void**)&P, g_P);
    cudaGetSymbolAddress((void**)&Y4, g_Y4);
    cudaGetSymbolAddress((void**)&cb1, g_cb1);
    cudaGetSymbolAddress((void**)&cb2, g_cb2);

    const double invBN = 1.0 / (double)BNT;

    // dynamic smem: (2*128*36 + 2*32*136) * 4 bytes = 71680
    constexpr int GEMM_SMEM = (2 * 128 * 36 + 2 * 32 * 136) * 4;
    cudaFuncSetAttribute(k_gemm_mma<64, 128, true, false>,
                         cudaFuncAttributeMaxDynamicSharedMemorySize, GEMM_SMEM);
    cudaFuncSetAttribute(k_gemm_mma<128, 512, false, true>,
                         cudaFuncAttributeMaxDynamicSharedMemorySize, GEMM_SMEM);

    k_init<<<32, 256>>>(st, pmax, pmin);

    // features + e1 linear (stats fused)
    k_feat_e1<<<BNT / 128, 128>>>(data, knn, e1_w, e1_b, Y1, st + ST1);
    k_finalize<<<1, 256>>>(st + ST1, e1_g, e1_be, ab + AB1, 64, invBN);

    // gcn1: aggregate (fused bn+relu) then compensated-TF32 GEMM (stats fused)
    k_aggregate<64><<<BNT / 8, 256>>>(Y1, knn, ab + AB1, S1);
    k_gemm_mma<64, 128, true, false><<<dim3(BNT / 128, 1), 256, GEMM_SMEM>>>(
        S1, gc1_w, gc1_b, Y2, 1.f / 17.f, st + ST2, nullptr, nullptr);
    k_finalize<<<1, 256>>>(st + ST2, g1_g, g1_be, ab + AB2, 128, invBN);

    // gcn2: aggregate then compensated-TF32 GEMM with fully fused epilogue
    // (no Y3 tensor at all: stats + per-(batch,channel) extrema only)
    k_aggregate<128><<<BNT / 8, 256>>>(Y2, knn, ab + AB2, S2);
    k_gemm_mma<128, 512, false, true><<<dim3(BNT / 128, 4), 256, GEMM_SMEM>>>(
        S2, gc2_w, gc2_b, nullptr, 1.f / 17.f, st + ST3, pmax, pmin);

    // bn3 + monotone pooled relu
    k_f3pool<<<16, 512>>>(st + ST3, pmax, pmin, g2_g, g2_be, P);

    // e2 linear + bn4 (over 16 samples) + codeword projections
    k_e2<<<16, 512>>>(P, e2_w, e2_b, Y4, st + ST4);
    k_finalize<<<2, 256>>>(st + ST4, e2_g, e2_be, ab + AB4, 512, 1.0 / 16.0);
    k_cw<<<16, 512>>>(ab + AB4, Y4, d1_w, d2_w, cb1, cb2);

    // decode
    k_decode1<<<BNT / 256, 256>>>(cb1, d1_w, d1_b, Y5, st + ST5);
    k_finalize<<<1, 32>>>(st + ST5, d1_g, d1_be, ab + AB5, 3, invBN);
    k_decode2<<<BNT / 256, 256>>>(Y5, ab + AB5, cb2, d2_w, d2_b, Y6, st + ST6);
    k_finalize<<<1, 32>>>(st + ST6, d2_g, d2_be, ab + AB6, 3, invBN);
    k_out<<<BNT / 256, 256>>>(Y6, ab + AB6, out);
}

// round 15
// speedup vs baseline: 1.5020x; 1.1430x over previous
#include <cuda_runtime.h>
#include <cuda_bf16.h>
#include <math.h>
#include <stdint.h>

// ---------------- constants ----------------
namespace {
constexpr int B_   = 16;
constexpr int N_   = 8192;
constexpr int BNT  = B_ * N_;       // 131072
constexpr int KNN_ = 16;
constexpr float EPS_ = 1e-5f;

// double-stat segment offsets: [sum(C), sq(C)] per stage
constexpr int ST1 = 0;              // 64 ch  -> 128
constexpr int ST2 = 128;            // 128 ch -> 256
constexpr int ST3 = 384;            // 512 ch -> 1024
constexpr int ST4 = 1408;           // 512 ch -> 1024
constexpr int ST5 = 2432;           // 3 ch   -> 6
constexpr int ST6 = 2438;           // 3 ch   -> 6
constexpr int STTOT = 2444;

// bn (a,b) float segment offsets
constexpr int AB1 = 0;              // 64  -> 128
constexpr int AB2 = 128;            // 128 -> 256
constexpr int AB4 = 384;            // 512 -> 1024
constexpr int AB5 = 1408;           // 3 -> 6
constexpr int AB6 = 1414;           // 3 -> 6
constexpr int ABTOT = 1420;
}

// ---------------- scratch (static device allocations; no cudaMalloc) ----------------
__device__ float    g_Y1[(size_t)BNT * 64];
__device__ float    g_S1[(size_t)BNT * 64];
__device__ float    g_Y2[(size_t)BNT * 128];
__device__ float    g_S2[(size_t)BNT * 128];
__device__ float    g_Y5[(size_t)BNT * 3];
__device__ float    g_Y6[(size_t)BNT * 3];
__device__ double   g_st[STTOT];
__device__ float    g_ab[ABTOT];
__device__ unsigned g_pmax[B_ * 512];
__device__ unsigned g_pmin[B_ * 512];
__device__ float    g_P[B_ * 512];
__device__ float    g_Y4[B_ * 512];
__device__ float    g_cb1[B_ * 3];
__device__ float    g_cb2[B_ * 3];

// ---------------- helpers ----------------
__device__ __forceinline__ unsigned fenc(float f) {
    unsigned u = __float_as_uint(f);
    return (u & 0x80000000u) ? ~u : (u | 0x80000000u);
}
__device__ __forceinline__ float fdec(unsigned u) {
    u = (u & 0x80000000u) ? (u & 0x7fffffffu) : ~u;
    return __uint_as_float(u);
}
// split (a,b) into packed-bf16x2 hi and lo words (hi+lo ~ 16 mantissa bits each)
__device__ __forceinline__ void bfsplit2(float a, float b, uint32_t& h, uint32_t& l) {
    __nv_bfloat162 hh = __floats2bfloat162_rn(a, b);
    float ra = a - __bfloat162float(hh.x);
    float rb = b - __bfloat162float(hh.y);
    __nv_bfloat162 ll = __floats2bfloat162_rn(ra, rb);
    h = *reinterpret_cast<uint32_t*>(&hh);
    l = *reinterpret_cast<uint32_t*>(&ll);
}
__device__ __forceinline__ void mma_bf16(float c[4], uint32_t a0, uint32_t a1,
                                         uint32_t a2, uint32_t a3,
                                         uint32_t b0, uint32_t b1) {
    asm volatile(
        "mma.sync.aligned.m16n8k16.row.col.f32.bf16.bf16.f32 "
        "{%0,%1,%2,%3}, {%4,%5,%6,%7}, {%8,%9}, {%0,%1,%2,%3};"
        : "+f"(c[0]), "+f"(c[1]), "+f"(c[2]), "+f"(c[3])
        : "r"(a0), "r"(a1), "r"(a2), "r"(a3), "r"(b0), "r"(b1));
}

// block-wide reduce of 3-channel (sum, sumsq) -> atomic into st[0..5]
// blockDim.x must be 256 (8 warps)
__device__ __forceinline__ void block_stats3(const float y0, const float y1, const float y2,
                                             double* st) {
    float v[6] = {y0, y1, y2, y0 * y0, y1 * y1, y2 * y2};
#pragma unroll
    for (int i = 0; i < 6; i++)
#pragma unroll
        for (int o = 16; o > 0; o >>= 1)
            v[i] += __shfl_down_sync(0xffffffffu, v[i], o);
    __shared__ float sm[8][6];
    int lane = threadIdx.x & 31, w = threadIdx.x >> 5;
    if (lane == 0) {
#pragma unroll
        for (int i = 0; i < 6; i++) sm[w][i] = v[i];
    }
    __syncthreads();
    if (threadIdx.x < 6) {
        float acc = 0.f;
#pragma unroll
        for (int i = 0; i < 8; i++) acc += sm[i][threadIdx.x];
        atomicAdd(&st[threadIdx.x], (double)acc);
    }
    __syncthreads();
}

// ---------------- kernels ----------------

__global__ void k_init(double* st, unsigned* pmax, unsigned* pmin) {
    int t = blockIdx.x * blockDim.x + threadIdx.x;
    if (t < STTOT) st[t] = 0.0;
    if (t < B_ * 512) { pmax[t] = 0u; pmin[t] = 0xFFFFFFFFu; }
}

// cov features + Linear(12,64) + fused column stats; block = 128 threads = 128 nodes
__global__ void k_feat_e1(const float* __restrict__ data, const int* __restrict__ knn,
                          const float* __restrict__ w, const float* __restrict__ bias,
                          float* __restrict__ Y1, double* __restrict__ st1) {
    __shared__ float ws[12 * 64];
    __shared__ float bs[64];
    __shared__ float xs[128][12];
    __shared__ float sred[128], qred[128];
    int tid = threadIdx.x;
    for (int i = tid; i < 12 * 64; i += 128) ws[i] = w[i];
    if (tid < 64) bs[tid] = bias[tid];

    int tnode = blockIdx.x * 128 + tid;
    int b = tnode >> 13;
    int n = tnode & (N_ - 1);
    const float* db = data + (size_t)b * N_ * 3;
    const int* kn = knn + (size_t)tnode * KNN_;

    float sx = 0, sy = 0, sz = 0;
    float sxx = 0, sxy = 0, sxz = 0, syy = 0, syz = 0, szz = 0;
#pragma unroll
    for (int j = 0; j < KNN_; j++) {
        int id = kn[j];
        float x = db[id * 3 + 0], y = db[id * 3 + 1], z = db[id * 3 + 2];
        sx += x; sy += y; sz += z;
        sxx += x * x; sxy += x * y; sxz += x * z;
        syy += y * y; syz += y * z; szz += z * z;
    }
    const float i16 = 1.f / 16.f, i15 = 1.f / 15.f;
    float mx = sx * i16, my = sy * i16, mz = sz * i16;
    float c00 = (sxx - 16.f * mx * mx) * i15;
    float c01 = (sxy - 16.f * mx * my) * i15;
    float c02 = (sxz - 16.f * mx * mz) * i15;
    float c11 = (syy - 16.f * my * my) * i15;
    float c12 = (syz - 16.f * my * mz) * i15;
    float c22 = (szz - 16.f * mz * mz) * i15;
    xs[tid][0] = db[n * 3 + 0];
    xs[tid][1] = db[n * 3 + 1];
    xs[tid][2] = db[n * 3 + 2];
    xs[tid][3] = c00; xs[tid][4] = c01; xs[tid][5] = c02;
    xs[tid][6] = c01; xs[tid][7] = c11; xs[tid][8] = c12;
    xs[tid][9] = c02; xs[tid][10] = c12; xs[tid][11] = c22;
    __syncthreads();

    int c = tid & 63;
    int ns = tid >> 6;  // 0..1
    size_t rowbase = (size_t)blockIdx.x * 128;
    float ssum = 0.f, sq = 0.f;
    for (int nr = ns; nr < 128; nr += 2) {
        float y = bs[c];
#pragma unroll
        for (int k = 0; k < 12; k++) y = fmaf(xs[nr][k], ws[k * 64 + c], y);
        Y1[(rowbase + nr) * 64 + c] = y;
        ssum += y; sq += y * y;
    }
    sred[tid] = ssum; qred[tid] = sq;
    __syncthreads();
    if (tid < 64) {
        atomicAdd(&st1[tid], (double)(sred[tid] + sred[tid + 64]));
        atomicAdd(&st1[64 + tid], (double)(qred[tid] + qred[tid + 64]));
    }
}

__global__ void k_finalize(const double* __restrict__ st, const float* __restrict__ g,
                           const float* __restrict__ be, float* __restrict__ ab,
                           int C, double inv) {
    int c = blockIdx.x * blockDim.x + threadIdx.x;
    if (c < C) {
        float m = (float)(st[c] * inv);
        float v = (float)(st[C + c] * inv) - m * m;
        float a = g[c] * rsqrtf(v + EPS_);
        ab[c] = a;
        ab[C + c] = be[c] - a * m;
    }
}

// S[i] = f(Y[i]) + sum_j f(Y[knn_j]),  f = relu(a*y+b).  warp per node, blockDim=256
template <int C>
__global__ void k_aggregate(const float* __restrict__ Y, const int* __restrict__ knn,
                            const float* __restrict__ ab, float* __restrict__ S) {
    constexpr int V = C / 32;
    int gw = (blockIdx.x * blockDim.x + threadIdx.x) >> 5;
    int lane = threadIdx.x & 31;
    int b = gw >> 13;
    int n = gw & (N_ - 1);
    float av[V], sv[V], acc[V];
#pragma unroll
    for (int v = 0; v < V; v++) {
        av[v] = ab[lane * V + v];
        sv[v] = ab[C + lane * V + v];
        acc[v] = 0.f;
    }
    const int* kn = knn + (size_t)gw * KNN_;
    int idxs[17];
    idxs[0] = n;
#pragma unroll
    for (int j = 0; j < KNN_; j++) idxs[j + 1] = kn[j];
    size_t bbase = (size_t)b * N_;
#pragma unroll 4
    for (int j = 0; j < 17; j++) {
        const float* row = Y + (bbase + idxs[j]) * C;
        if constexpr (C == 64) {
            float2 val = reinterpret_cast<const float2*>(row)[lane];
            acc[0] += fmaxf(fmaf(av[0], val.x, sv[0]), 0.f);
            acc[1] += fmaxf(fmaf(av[1], val.y, sv[1]), 0.f);
        } else {
            float4 val = reinterpret_cast<const float4*>(row)[lane];
            acc[0] += fmaxf(fmaf(av[0], val.x, sv[0]), 0.f);
            acc[1] += fmaxf(fmaf(av[1], val.y, sv[1]), 0.f);
            acc[2] += fmaxf(fmaf(av[2], val.z, sv[2]), 0.f);
            acc[3] += fmaxf(fmaf(av[3], val.w, sv[3]), 0.f);
        }
    }
    float* out = S + (size_t)gw * C;
    if constexpr (C == 64) {
        reinterpret_cast<float2*>(out)[lane] = make_float2(acc[0], acc[1]);
    } else {
        reinterpret_cast<float4*>(out)[lane] = make_float4(acc[0], acc[1], acc[2], acc[3]);
    }
}

// ---------------- error-compensated BF16 tensor GEMM (3-MMA split, m16n8k16) ----------------
// Out[M,ND] = (A[M,KD] @ W[KD,ND]) * scale + bias.
// Each operand split into bf16 hi+lo (packed bf16x2 along k); hi*hi + lo*hi + hi*lo
// accumulated in fp32 -> ~2^-18 relative residual on the tensor pipe at k=16/instr.
// Fused epilogue: column sums/sumsq -> st; optional per-(batch,col) extrema.
// 256 threads = 8 warps (2 M x 4 N), 128x128 tile, warp tile 64x32.
template <int KD, int ND, bool STORE, bool EXTREMA>
__global__ void __launch_bounds__(256)
k_gemm_mma(const float* __restrict__ A, const float* __restrict__ W,
           const float* __restrict__ bias, float* __restrict__ Out, float scale,
           double* __restrict__ st, unsigned* __restrict__ pmax,
           unsigned* __restrict__ pmin) {
    constexpr int LDA = 20;    // packed k-words per A row (16 used + pad; banks distinct)
    constexpr int LDB = 136;   // n-words per B kp-row (128 used + pad; banks distinct)
    __shared__ uint32_t As_h[128 * LDA], As_l[128 * LDA];
    __shared__ uint32_t Bs_h[16 * LDB],  Bs_l[16 * LDB];

    int tid = threadIdx.x;
    int lane = tid & 31, wid = tid >> 5;
    int warp_m = wid >> 2, warp_n = wid & 3;
    size_t bm0 = (size_t)blockIdx.x * 128;
    int bn0 = blockIdx.y * 128;

    float acc[4][4][4];
#pragma unroll
    for (int i = 0; i < 4; i++)
#pragma unroll
        for (int j = 0; j < 4; j++)
#pragma unroll
            for (int r = 0; r < 4; r++) acc[i][j][r] = 0.f;

    int am = tid >> 3;           // 0..31
    int ak = (tid & 7) * 4;      // 0..28 (fp32 k offset)
    int bkp0 = tid >> 5;         // 0..7  (packed k-pair row)
    int bnc = (tid & 31) * 4;    // 0..124

    for (int k0 = 0; k0 < KD; k0 += 32) {
        // ---- fill A tile: pack (k even, k odd) into bf16x2 hi/lo ----
#pragma unroll
        for (int i = 0; i < 4; i++) {
            int m = am + 32 * i;
            float4 v = *reinterpret_cast<const float4*>(A + (bm0 + m) * KD + k0 + ak);
            uint32_t h0, l0, h1, l1;
            bfsplit2(v.x, v.y, h0, l0);
            bfsplit2(v.z, v.w, h1, l1);
            *reinterpret_cast<uint2*>(&As_h[m * LDA + (ak >> 1)]) = make_uint2(h0, h1);
            *reinterpret_cast<uint2*>(&As_l[m * LDA + (ak >> 1)]) = make_uint2(l0, l1);
        }
        // ---- fill B tile: pack (W[k][n], W[k+1][n]) along k ----
#pragma unroll
        for (int j = 0; j < 2; j++) {
            int kp = bkp0 + 8 * j;          // 0..15
            int k = k0 + 2 * kp;
            float4 r0 = *reinterpret_cast<const float4*>(W + (size_t)k * ND + bn0 + bnc);
            float4 r1 = *reinterpret_cast<const float4*>(W + (size_t)(k + 1) * ND + bn0 + bnc);
            uint4 h4, l4;
            bfsplit2(r0.x, r1.x, h4.x, l4.x);
            bfsplit2(r0.y, r1.y, h4.y, l4.y);
            bfsplit2(r0.z, r1.z, h4.z, l4.z);
            bfsplit2(r0.w, r1.w, h4.w, l4.w);
            *reinterpret_cast<uint4*>(&Bs_h[kp * LDB + bnc]) = h4;
            *reinterpret_cast<uint4*>(&Bs_l[kp * LDB + bnc]) = l4;
        }
        __syncthreads();
#pragma unroll
        for (int kg = 0; kg < 2; kg++) {       // two k16 groups per k32 tile
            int kk = kg * 8 + (lane & 3);      // packed-pair index
            uint32_t bh[4][2], bl[4][2];
#pragma unroll
            for (int nt = 0; nt < 4; nt++) {
                int n = warp_n * 32 + nt * 8 + (lane >> 2);
                bh[nt][0] = Bs_h[kk * LDB + n];
                bh[nt][1] = Bs_h[(kk + 4) * LDB + n];
                bl[nt][0] = Bs_l[kk * LDB + n];
                bl[nt][1] = Bs_l[(kk + 4) * LDB + n];
            }
#pragma unroll
            for (int mt = 0; mt < 4; mt++) {
                int r = warp_m * 64 + mt * 16 + (lane >> 2);
                uint32_t ah0 = As_h[r * LDA + kk];
                uint32_t ah1 = As_h[(r + 8) * LDA + kk];
                uint32_t ah2 = As_h[r * LDA + kk + 4];
                uint32_t ah3 = As_h[(r + 8) * LDA + kk + 4];
                uint32_t al0 = As_l[r * LDA + kk];
                uint32_t al1 = As_l[(r + 8) * LDA + kk];
                uint32_t al2 = As_l[r * LDA + kk + 4];
                uint32_t al3 = As_l[(r + 8) * LDA + kk + 4];
#pragma unroll
                for (int nt = 0; nt < 4; nt++) {
                    mma_bf16(acc[mt][nt], al0, al1, al2, al3, bh[nt][0], bh[nt][1]);
                    mma_bf16(acc[mt][nt], ah0, ah1, ah2, ah3, bl[nt][0], bl[nt][1]);
                    mma_bf16(acc[mt][nt], ah0, ah1, ah2, ah3, bh[nt][0], bh[nt][1]);
                }
            }
        }
        __syncthreads();
    }

    // ---- epilogue: scale+bias, optional store, fused column stats ----
    float bsv[8];
#pragma unroll
    for (int nt = 0; nt < 4; nt++) {
        int c0 = bn0 + warp_n * 32 + nt * 8 + (lane & 3) * 2;
        bsv[nt * 2 + 0] = bias[c0];
        bsv[nt * 2 + 1] = bias[c0 + 1];
    }
    float s[8], q[8], mxv[8], mnv[8];
#pragma unroll
    for (int i = 0; i < 8; i++) { s[i] = 0.f; q[i] = 0.f; mxv[i] = -3.4e38f; mnv[i] = 3.4e38f; }

#pragma unroll
    for (int mt = 0; mt < 4; mt++) {
        size_t r = bm0 + warp_m * 64 + mt * 16 + (lane >> 2);
#pragma unroll
        for (int nt = 0; nt < 4; nt++) {
            float y0 = fmaf(acc[mt][nt][0], scale, bsv[nt * 2 + 0]);
            float y1 = fmaf(acc[mt][nt][1], scale, bsv[nt * 2 + 1]);
            float y2 = fmaf(acc[mt][nt][2], scale, bsv[nt * 2 + 0]);
            float y3 = fmaf(acc[mt][nt][3], scale, bsv[nt * 2 + 1]);
            if constexpr (STORE) {
                int c0 = bn0 + warp_n * 32 + nt * 8 + (lane & 3) * 2;
                *reinterpret_cast<float2*>(Out + r * ND + c0) = make_float2(y0, y1);
                *reinterpret_cast<float2*>(Out + (r + 8) * ND + c0) = make_float2(y2, y3);
            }
            int i0 = nt * 2, i1 = nt * 2 + 1;
            s[i0] += y0 + y2; q[i0] += y0 * y0 + y2 * y2;
            s[i1] += y1 + y3; q[i1] += y1 * y1 + y3 * y3;
            if constexpr (EXTREMA) {
                mxv[i0] = fmaxf(mxv[i0], fmaxf(y0, y2));
                mnv[i0] = fminf(mnv[i0], fminf(y0, y2));
                mxv[i1] = fmaxf(mxv[i1], fmaxf(y1, y3));
                mnv[i1] = fminf(mnv[i1], fminf(y1, y3));
            }
        }
    }
    // reduce across lanes sharing a column (lane>>2 axis): xor offsets 4,8,16
#pragma unroll
    for (int o = 4; o <= 16; o <<= 1) {
#pragma unroll
        for (int i = 0; i < 8; i++) {
            s[i] += __shfl_xor_sync(0xffffffffu, s[i], o);
            q[i] += __shfl_xor_sync(0xffffffffu, q[i], o);
            if constexpr (EXTREMA) {
                mxv[i] = fmaxf(mxv[i], __shfl_xor_sync(0xffffffffu, mxv[i], o));
                mnv[i] = fminf(mnv[i], __shfl_xor_sync(0xffffffffu, mnv[i], o));
            }
        }
    }
    if (lane < 4) {
        int b = (int)(bm0 >> 13);
#pragma unroll
        for (int i = 0; i < 8; i++) {
            int c = bn0 + warp_n * 32 + (i >> 1) * 8 + lane * 2 + (i & 1);
            atomicAdd(&st[c], (double)s[i]);
            atomicAdd(&st[ND + c], (double)q[i]);
            if constexpr (EXTREMA) {
                atomicMax(&pmax[b * 512 + c], fenc(mxv[i]));
                atomicMin(&pmin[b * 512 + c], fenc(mnv[i]));
            }
        }
    }
}

// bn3 + monotone pooled relu.  grid=16 (batch), blockDim=512
__global__ void k_f3pool(const double* __restrict__ st3, const unsigned* __restrict__ pmax,
                         const unsigned* __restrict__ pmin, const float* __restrict__ g,
                         const float* __restrict__ be, float* __restrict__ P) {
    int b = blockIdx.x, c = threadIdx.x;
    double inv = 1.0 / (double)BNT;
    float m = (float)(st3[c] * inv);
    float v = (float)(st3[512 + c] * inv) - m * m;
    float a = g[c] * rsqrtf(v + EPS_);
    float sh = be[c] - a * m;
    float e = (a >= 0.f) ? fdec(pmax[b * 512 + c]) : fdec(pmin[b * 512 + c]);
    P[b * 512 + c] = fmaxf(fmaf(a, e, sh), 0.f);
}

// e2 linear: Y4 = P @ e2_w + e2_b, plus st4.  grid=16, blockDim=512
__global__ void k_e2(const float* __restrict__ P, const float* __restrict__ w,
                     const float* __restrict__ bias, float* __restrict__ Y4,
                     double* __restrict__ st4) {
    __shared__ float pr[512];
    int b = blockIdx.x, c = threadIdx.x;
    pr[c] = P[b * 512 + c];
    __syncthreads();
    float y = bias[c];
    for (int k = 0; k < 512; k++) y = fmaf(pr[k], w[k * 512 + c], y);
    Y4[b * 512 + c] = y;
    atomicAdd(&st4[c], (double)y);
    atomicAdd(&st4[512 + c], (double)(y * y));
}

// cw = relu(bn4(Y4)); cb1 = cw @ d1_w[:512], cb2 = cw @ d2_w[:512].  grid=16, blockDim=512
__global__ void k_cw(const float* __restrict__ ab4, const float* __restrict__ Y4,
                     const float* __restrict__ d1w, const float* __restrict__ d2w,
                     float* __restrict__ cb1, float* __restrict__ cb2) {
    __shared__ float cwsh[512];
    __shared__ float red[512];
    int b = blockIdx.x, c = threadIdx.x;
    float a = ab4[c], sh = ab4[512 + c];
    cwsh[c] = fmaxf(fmaf(a, Y4[b * 512 + c], sh), 0.f);
    __syncthreads();
    for (int d = 0; d < 6; d++) {
        const float* W = (d < 3) ? d1w : d2w;
        int j = (d < 3) ? d : d - 3;
        red[c] = cwsh[c] * W[c * 3 + j];
        __syncthreads();
        for (int s = 256; s > 0; s >>= 1) {
            if (c < s) red[c] += red[c + s];
            __syncthreads();
        }
        if (c == 0) { ((d < 3) ? cb1 : cb2)[b * 3 + j] = red[0]; }
        __syncthreads();
    }
}

// decode stage 1: Y5 = cb1[b] + grid @ d1_w[512:514] + d1_b, + st5.  blockDim=256
__global__ void k_decode1(const float* __restrict__ cb1, const float* __restrict__ d1w,
                          const float* __restrict__ d1b, float* __restrict__ Y5,
                          double* __restrict__ st5) {
    int t = blockIdx.x * 256 + threadIdx.x;
    int b = t >> 13, n = t & (N_ - 1);
    int ix = n / 65, iy = n % 65;
    float gx = 1.f + (float)ix * (119.f / 128.f);
    float gy = 1.f + (float)iy * (59.f / 64.f);
    float y[3];
#pragma unroll
    for (int j = 0; j < 3; j++) {
        y[j] = cb1[b * 3 + j] + gx * d1w[512 * 3 + j] + gy * d1w[513 * 3 + j] + d1b[j];
        Y5[(size_t)t * 3 + j] = y[j];
    }
    block_stats3(y[0], y[1], y[2], st5);
}

// decode stage 2: z1 = relu(bn5(Y5)); Y6 = cb2[b] + z1 @ d2_w[512:515] + d2_b, + st6
__global__ void k_decode2(const float* __restrict__ Y5, const float* __restrict__ ab5,
                          const float* __restrict__ cb2, const float* __restrict__ d2w,
                          const float* __restrict__ d2b, float* __restrict__ Y6,
                          double* __restrict__ st6) {
    int t = blockIdx.x * 256 + threadIdx.x;
    int b = t >> 13;
    float z[3];
#pragma unroll
    for (int i = 0; i < 3; i++) {
        float v = Y5[(size_t)t * 3 + i];
        z[i] = fmaxf(fmaf(ab5[i], v, ab5[3 + i]), 0.f);
    }
    float y[3];
#pragma unroll
    for (int j = 0; j < 3; j++) {
        float v = cb2[b * 3 + j] + d2b[j];
#pragma unroll
        for (int i = 0; i < 3; i++) v = fmaf(z[i], d2w[(512 + i) * 3 + j], v);
        y[j] = v;
        Y6[(size_t)t * 3 + j] = v;
    }
    block_stats3(y[0], y[1], y[2], st6);
}

__global__ void k_out(const float* __restrict__ Y6, const float* __restrict__ ab6,
                      float* __restrict__ out) {
    int t = blockIdx.x * 256 + threadIdx.x;
#pragma unroll
    for (int j = 0; j < 3; j++) {
        float v = Y6[(size_t)t * 3 + j];
        out[(size_t)t * 3 + j] = fmaxf(fmaf(ab6[j], v, ab6[3 + j]), 0.f);
    }
}

// ---------------- launch ----------------
extern "C" void kernel_launch(void* const* d_in, const int* in_sizes, int n_in,
                              void* d_out, int out_size) {
    (void)in_sizes; (void)n_in; (void)out_size;
    const float* data  = (const float*)d_in[0];
    const int*   knn   = (const int*)d_in[1];
    const float* e1_w  = (const float*)d_in[2];
    const float* e1_b  = (const float*)d_in[3];
    const float* e1_g  = (const float*)d_in[4];
    const float* e1_be = (const float*)d_in[5];
    const float* gc1_w = (const float*)d_in[6];
    const float* gc1_b = (const float*)d_in[7];
    const float* g1_g  = (const float*)d_in[8];
    const float* g1_be = (const float*)d_in[9];
    const float* gc2_w = (const float*)d_in[10];
    const float* gc2_b = (const float*)d_in[11];
    const float* g2_g  = (const float*)d_in[12];
    const float* g2_be = (const float*)d_in[13];
    const float* e2_w  = (const float*)d_in[14];
    const float* e2_b  = (const float*)d_in[15];
    const float* e2_g  = (const float*)d_in[16];
    const float* e2_be = (const float*)d_in[17];
    const float* d1_w  = (const float*)d_in[18];
    const float* d1_b  = (const float*)d_in[19];
    const float* d1_g  = (const float*)d_in[20];
    const float* d1_be = (const float*)d_in[21];
    const float* d2_w  = (const float*)d_in[22];
    const float* d2_b  = (const float*)d_in[23];
    const float* d2_g  = (const float*)d_in[24];
    const float* d2_be = (const float*)d_in[25];
    float* out = (float*)d_out;

    float *Y1, *S1, *Y2, *S2, *Y5, *Y6, *ab, *P, *Y4, *cb1, *cb2;
    double* st;
    unsigned *pmax, *pmin;
    cudaGetSymbolAddress((void**)&Y1, g_Y1);
    cudaGetSymbolAddress((void**)&S1, g_S1);
    cudaGetSymbolAddress((void**)&Y2, g_Y2);
    cudaGetSymbolAddress((void**)&S2, g_S2);
    cudaGetSymbolAddress((void**)&Y5, g_Y5);
    cudaGetSymbolAddress((void**)&Y6, g_Y6);
    cudaGetSymbolAddress((void**)&st, g_st);
    cudaGetSymbolAddress((void**)&ab, g_ab);
    cudaGetSymbolAddress((void**)&pmax, g_pmax);
    cudaGetSymbolAddress((void**)&pmin, g_pmin);
    cudaGetSymbolAddress((void**)&P, g_P);
    cudaGetSymbolAddress((void**)&Y4, g_Y4);
    cudaGetSymbolAddress((void**)&cb1, g_cb1);
    cudaGetSymbolAddress((void**)&cb2, g_cb2);

    const double invBN = 1.0 / (double)BNT;

    k_init<<<32, 256>>>(st, pmax, pmin);

    // features + e1 linear (stats fused)
    k_feat_e1<<<BNT / 128, 128>>>(data, knn, e1_w, e1_b, Y1, st + ST1);
    k_finalize<<<1, 256>>>(st + ST1, e1_g, e1_be, ab + AB1, 64, invBN);

    // gcn1: aggregate (fused bn+relu) then compensated-BF16 tensor GEMM (stats fused)
    k_aggregate<64><<<BNT / 8, 256>>>(Y1, knn, ab + AB1, S1);
    k_gemm_mma<64, 128, true, false><<<dim3(BNT / 128, 1), 256>>>(
        S1, gc1_w, gc1_b, Y2, 1.f / 17.f, st + ST2, nullptr, nullptr);
    k_finalize<<<1, 256>>>(st + ST2, g1_g, g1_be, ab + AB2, 128, invBN);

    // gcn2: aggregate then compensated-BF16 GEMM with fully fused epilogue
    // (no Y3 tensor at all: stats + per-(batch,channel) extrema only)
    k_aggregate<128><<<BNT / 8, 256>>>(Y2, knn, ab + AB2, S2);
    k_gemm_mma<128, 512, false, true><<<dim3(BNT / 128, 4), 256>>>(
        S2, gc2_w, gc2_b, nullptr, 1.f / 17.f, st + ST3, pmax, pmin);

    // bn3 + monotone pooled relu
    k_f3pool<<<16, 512>>>(st + ST3, pmax, pmin, g2_g, g2_be, P);

    // e2 linear + bn4 (over 16 samples) + codeword projections
    k_e2<<<16, 512>>>(P, e2_w, e2_b, Y4, st + ST4);
    k_finalize<<<2, 256>>>(st + ST4, e2_g, e2_be, ab + AB4, 512, 1.0 / 16.0);
    k_cw<<<16, 512>>>(ab + AB4, Y4, d1_w, d2_w, cb1, cb2);

    // decode
    k_decode1<<<BNT / 256, 256>>>(cb1, d1_w, d1_b, Y5, st + ST5);
    k_finalize<<<1, 32>>>(st + ST5, d1_g, d1_be, ab + AB5, 3, invBN);
    k_decode2<<<BNT / 256, 256>>>(Y5, ab + AB5, cb2, d2_w, d2_b, Y6, st + ST6);
    k_finalize<<<1, 32>>>(st + ST6, d2_g, d2_be, ab + AB6, 3, invBN);
    k_out<<<BNT / 256, 256>>>(Y6, ab + AB6, out);
}